// round 16
// baseline (speedup 1.0000x reference)
#include <cuda_runtime.h>
#include <cuda_fp16.h>
#include <math.h>

#define D        32
#define TSMAX    9
#define NTT      256           // train per tile
#define MQ       256           // queries per CTA
#define M_MAX    16384
#define N_MAX    8192
#define EPSV     1e-8f
#define BWB      64

// smem pitch-80 rows. Buf: Bh[0,20480) ext[20480,22528)
#define PITCH    80
#define OFFEXT   20480
#define BUFSZ    22528
#define SMEMSZ   (2*BUFSZ)     // 45056 (<48KB static); A staging (20480) aliases buf0

__device__ float        g_cl;
__device__ __half       g_Ah[M_MAX * D];    // fp16(x)
__device__ __half       g_Bh[N_MAX * D];    // fp16(t)
__device__ float4       g_ext4[N_MAX / 2];  // {t2q_even, t2q_odd, r_even, r_odd}
__device__ float        g_qe[M_MAX];        // q2 from quantized
__device__ double       g_bws [BWB * D];
__device__ double       g_bws2[BWB * D];
__device__ float        g_pnum[TSMAX][M_MAX];
__device__ float        g_pden[TSMAX][M_MAX];
__device__ unsigned int g_rmin, g_rmax, g_smin, g_smax;
__device__ unsigned int g_cnt;              // redfin barrier (reset by prepbw)
__device__ unsigned int g_bwcnt;            // prepbw bw-block arrival counter

// ---------------- helpers ----------------
__device__ __forceinline__ unsigned long long pack2(float lo, float hi) {
    unsigned long long r; asm("mov.b64 %0, {%1, %2};" : "=l"(r) : "f"(lo), "f"(hi)); return r;
}
__device__ __forceinline__ unsigned long long dup2(float v) {
    unsigned long long r; asm("mov.b64 %0, {%1, %1};" : "=l"(r) : "f"(v)); return r;
}
__device__ __forceinline__ unsigned long long fma2(unsigned long long a, unsigned long long b, unsigned long long c) {
    unsigned long long d; asm("fma.rn.f32x2 %0, %1, %2, %3;" : "=l"(d) : "l"(a), "l"(b), "l"(c)); return d;
}
__device__ __forceinline__ float2 unpack2(unsigned long long p) {
    float2 f; asm("mov.b64 {%0, %1}, %2;" : "=f"(f.x), "=f"(f.y) : "l"(p)); return f;
}
__device__ __forceinline__ float ex2f(float a) {
    float r; asm("ex2.approx.f32 %0, %1;" : "=f"(r) : "f"(a)); return r;
}
__device__ __forceinline__ void cp16(unsigned dst, const void* src) {
    asm volatile("cp.async.ca.shared.global [%0], [%1], 16;" :: "r"(dst), "l"(src));
}
__device__ __forceinline__ unsigned fenc(float f) {
    unsigned u = __float_as_uint(f); return (u & 0x80000000u) ? ~u : (u | 0x80000000u);
}
__device__ __forceinline__ float fdec(unsigned u) {
    u = (u & 0x80000000u) ? (u & 0x7fffffffu) : ~u; return __uint_as_float(u);
}
__device__ __forceinline__ float warp_min(float v) {
    #pragma unroll
    for (int o = 16; o; o >>= 1) v = fminf(v, __shfl_xor_sync(~0u, v, o));
    return v;
}
__device__ __forceinline__ float warp_max(float v) {
    #pragma unroll
    for (int o = 16; o; o >>= 1) v = fmaxf(v, __shfl_xor_sync(~0u, v, o));
    return v;
}
__device__ __forceinline__ void ldmx4(unsigned* r, unsigned addr) {
    asm volatile("ldmatrix.sync.aligned.m8n8.x4.shared.b16 {%0,%1,%2,%3}, [%4];"
                 : "=r"(r[0]), "=r"(r[1]), "=r"(r[2]), "=r"(r[3]) : "r"(addr));
}
__device__ __forceinline__ void mma_f16(float* c, const unsigned* a, unsigned b0, unsigned b1) {
    asm volatile("mma.sync.aligned.m16n8k16.row.col.f32.f16.f16.f32 "
                 "{%0,%1,%2,%3}, {%4,%5,%6,%7}, {%8,%9}, {%0,%1,%2,%3};"
                 : "+f"(c[0]), "+f"(c[1]), "+f"(c[2]), "+f"(c[3])
                 : "r"(a[0]), "r"(a[1]), "r"(a[2]), "r"(a[3]), "r"(b0), "r"(b1));
}

// ---------------- fused prep + bandwidth (phase 1 + last-block phase 2) ----------
__global__ void k_prepbw(const float* __restrict__ x, const float* __restrict__ tx,
                         const float* __restrict__ tr, int m, int n) {
    __shared__ double sds[8][8][4], sds2[8][8][4];
    __shared__ int s_last;
    const int tid = threadIdx.x;
    if (blockIdx.x < BWB) {
        const int b = blockIdx.x;
        const float4* tx4 = (const float4*)tx;
        double s[4] = {0,0,0,0}, s2[4] = {0,0,0,0};
        #pragma unroll
        for (int it = 0; it < 4; it++) {
            float4 v = tx4[(size_t)(b * 128 + it * 32) * 8 + tid];
            double vx = v.x, vy = v.y, vz = v.z, vw = v.w;
            s[0] += vx; s2[0] += vx*vx; s[1] += vy; s2[1] += vy*vy;
            s[2] += vz; s2[2] += vz*vz; s[3] += vw; s2[3] += vw*vw;
        }
        #pragma unroll
        for (int o = 8; o <= 16; o <<= 1)
            #pragma unroll
            for (int k = 0; k < 4; k++) {
                s[k]  += __shfl_xor_sync(~0u, s[k],  o);
                s2[k] += __shfl_xor_sync(~0u, s2[k], o);
            }
        int w = tid >> 5, l = tid & 31;
        if (l < 8)
            #pragma unroll
            for (int k = 0; k < 4; k++) { sds[w][l][k] = s[k]; sds2[w][l][k] = s2[k]; }
        __syncthreads();
        if (tid < 8)
            #pragma unroll
            for (int k = 0; k < 4; k++) {
                double a = 0, a2 = 0;
                #pragma unroll
                for (int ww = 0; ww < 8; ww++) { a += sds[ww][tid][k]; a2 += sds2[ww][tid][k]; }
                g_bws[b * D + tid * 4 + k] = a; g_bws2[b * D + tid * 4 + k] = a2;
            }
        __threadfence();
        __syncthreads();
        if (tid == 0) {
            unsigned old = atomicAdd(&g_bwcnt, 1u);
            s_last = (old == BWB - 1);
        }
        __syncthreads();
        if (s_last) {
            __threadfence();
            if (tid == 0) g_bwcnt = 0;                 // reset for next graph replay
            if (tid < 32) {
                int d = tid;
                double ss = 0, ss2 = 0;
                for (int bb = 0; bb < BWB; bb++) { ss += g_bws[bb * D + d]; ss2 += g_bws2[bb * D + d]; }
                double mean = ss / n, var = (ss2 - n * mean * mean) / (n - 1);
                double sd = sqrt(var > 0.0 ? var : 0.0);
                #pragma unroll
                for (int o = 16; o; o >>= 1) sd += __shfl_xor_sync(~0u, sd, o);
                if (d == 0) {
                    double bw = (sd / D) * exp(-log((double)n) / (D + 4));
                    g_cl = (float)(1.0 / (2.0 * bw * bw) * 1.4426950408889634);
                    g_rmin = ~0u; g_rmax = 0u; g_smin = ~0u; g_smax = 0u;
                    g_cnt = 0u;
                }
            }
        }
        return;
    }
    int idx = (blockIdx.x - BWB) * 256 + tid;
    int row = idx >> 3, g = idx & 7;
    const bool isq = (row < m);
    int r2 = isq ? row : row - m;
    const float4* src = isq ? (const float4*)x : (const float4*)tx;
    float4 v = src[(size_t)r2 * 8 + g];
    __half hx = __float2half_rn(v.x), hy = __float2half_rn(v.y);
    __half hz = __float2half_rn(v.z), hw = __float2half_rn(v.w);
    float qx = __half2float(hx), qy = __half2float(hy);
    float qz = __half2float(hz), qw = __half2float(hw);
    float s = fmaf(qx, qx, fmaf(qy, qy, fmaf(qz, qz, qw * qw)));
    s += __shfl_xor_sync(~0u, s, 1);
    s += __shfl_xor_sync(~0u, s, 2);
    s += __shfl_xor_sync(~0u, s, 4);
    uint2 hi;
    hi.x = (unsigned)__half_as_ushort(hx) | ((unsigned)__half_as_ushort(hy) << 16);
    hi.y = (unsigned)__half_as_ushort(hz) | ((unsigned)__half_as_ushort(hw) << 16);
    if (isq) {
        ((uint2*)g_Ah)[(size_t)r2 * 8 + g] = hi;
        if (g == 0) g_qe[r2] = s;
    } else {
        ((uint2*)g_Bh)[(size_t)r2 * 8 + g] = hi;
        if (g == 0) {
            float* e = (float*)&g_ext4[r2 >> 1];
            if (r2 & 1) { e[1] = s; e[3] = tr[r2]; }
            else        { e[0] = s; e[2] = tr[r2]; }
        }
    }
}

// ---------------- HMMA KDE mainloop: 8 warps x 32 queries, 256-tile, occ 4 ------
__device__ __forceinline__ void load_tile(unsigned sb, int g, int b, int tid) {
    unsigned base = sb + b * BUFSZ;
    const __half* sh = g_Bh + (size_t)g * NTT * D;
    #pragma unroll
    for (int i = 0; i < 4; i++) {
        int idx = tid + i * 256, row = idx >> 2, c = idx & 3;
        cp16(base + row * PITCH + c * 16, sh + row * D + c * 8);
    }
    if (tid < 128) cp16(base + OFFEXT + tid * 16, g_ext4 + (size_t)g * 128 + tid);
    asm volatile("cp.async.commit_group;" ::: "memory");
}

__global__ void __launch_bounds__(256, 4)
k_main_mma(int n) {
    __shared__ __align__(16) char smem[SMEMSZ];
    unsigned sb = (unsigned)__cvta_generic_to_shared(smem);
    const int tid = threadIdx.x, w = tid >> 5, lane = tid & 31;
    const int qblk  = blockIdx.x & 63;
    const int split = blockIdx.x >> 6;               // 0..8, grid = 576
    const int NTtot = n / NTT;                       // 32
    const int tb_lo = (split * NTtot) / TSMAX;
    const int tb_hi = ((split + 1) * NTtot) / TSMAX;

    // ---- stage A (256 rows, pitch 80) at sb, extract frags, reuse smem ----
    #pragma unroll
    for (int i = 0; i < 4; i++) {
        int idx = tid + i * 256, row = idx >> 2, c = idx & 3;
        cp16(sb + row * PITCH + c * 16, g_Ah + (size_t)(qblk * MQ + row) * D + c * 8);
    }
    asm volatile("cp.async.commit_group;" ::: "memory");
    asm volatile("cp.async.wait_group 0;" ::: "memory");
    __syncthreads();

    unsigned ah0[2][4], ah1[2][4];                   // warp owns rows w*32..w*32+31
    {
        unsigned rowsel = lane & 15, colb = (lane >> 4) * 16;
        unsigned ab0 = sb + (w * 32 + rowsel) * PITCH + colb;
        unsigned ab1 = ab0 + 16 * PITCH;
        ldmx4(ah0[0], ab0);
        ldmx4(ah0[1], ab0 + 32);
        ldmx4(ah1[0], ab1);
        ldmx4(ah1[1], ab1 + 32);
    }
    const int qg = lane >> 2;
    const float cl = g_cl;
    const unsigned long long negcl2 = dup2(-cl);
    const unsigned long long K2d    = dup2(cl + cl);
    const int qbase = qblk * MQ + w * 32;
    const unsigned long long cqa0 = dup2(-cl * g_qe[qbase + qg]);
    const unsigned long long cqb0 = dup2(-cl * g_qe[qbase + qg + 8]);
    const unsigned long long cqa1 = dup2(-cl * g_qe[qbase + qg + 16]);
    const unsigned long long cqb1 = dup2(-cl * g_qe[qbase + qg + 24]);
    __syncthreads();

    load_tile(sb, tb_lo, 0, tid);

    float na0 = 0.f, da0 = 0.f, nb0 = 0.f, db0 = 0.f;
    float na1 = 0.f, da1 = 0.f, nb1 = 0.f, db1 = 0.f;

    const unsigned browAdd = (lane >> 4) * 8 + (lane & 7);
    const unsigned bcolb   = ((lane >> 3) & 1) * 16;

    for (int tb = tb_lo; tb < tb_hi; tb++) {
        const int buf = (tb - tb_lo) & 1;
        if (tb + 1 < tb_hi) {
            load_tile(sb, tb + 1, buf ^ 1, tid);
            asm volatile("cp.async.wait_group 1;" ::: "memory");
        } else {
            asm volatile("cp.async.wait_group 0;" ::: "memory");
        }
        __syncthreads();

        const unsigned bbase = sb + buf * BUFSZ;
        const float4* ext = (const float4*)(smem + buf * BUFSZ + OFFEXT);

        #pragma unroll
        for (int np = 0; np < 16; np++) {
            const unsigned rb = bbase + (np * 16 + browAdd) * PITCH + bcolb;
            float c0[2][4], c1[2][4];
            #pragma unroll
            for (int s = 0; s < 2; s++)
                #pragma unroll
                for (int k = 0; k < 4; k++) { c0[s][k] = 0.f; c1[s][k] = 0.f; }

            #pragma unroll
            for (int ks = 0; ks < 2; ks++) {
                unsigned bv[4];
                ldmx4(bv, rb + ks * 32);
                mma_f16(c0[0], ah0[ks], bv[0], bv[1]);
                mma_f16(c0[1], ah0[ks], bv[2], bv[3]);
                mma_f16(c1[0], ah1[ks], bv[0], bv[1]);
                mma_f16(c1[1], ah1[ks], bv[2], bv[3]);
            }

            #pragma unroll
            for (int ns = 0; ns < 2; ns++) {
                float4 e = ext[(np * 2 + ns) * 4 + (lane & 3)];
                unsigned long long t2p = pack2(e.x, e.y);
                unsigned long long ba0 = fma2(t2p, negcl2, cqa0);
                unsigned long long bb0 = fma2(t2p, negcl2, cqb0);
                unsigned long long ba1 = fma2(t2p, negcl2, cqa1);
                unsigned long long bb1 = fma2(t2p, negcl2, cqb1);
                unsigned long long pa0 = fma2(pack2(c0[ns][0], c0[ns][1]), K2d, ba0);
                unsigned long long pb0 = fma2(pack2(c0[ns][2], c0[ns][3]), K2d, bb0);
                unsigned long long pa1 = fma2(pack2(c1[ns][0], c1[ns][1]), K2d, ba1);
                unsigned long long pb1 = fma2(pack2(c1[ns][2], c1[ns][3]), K2d, bb1);
                float2 f0 = unpack2(pa0), f1 = unpack2(pb0);
                float2 f2 = unpack2(pa1), f3 = unpack2(pb1);
                float w0 = ex2f(f0.x), w1 = ex2f(f0.y);
                float w2 = ex2f(f1.x), w3 = ex2f(f1.y);
                float w4 = ex2f(f2.x), w5 = ex2f(f2.y);
                float w6 = ex2f(f3.x), w7 = ex2f(f3.y);
                na0 = fmaf(w0, e.z, na0); na0 = fmaf(w1, e.w, na0); da0 += w0 + w1;
                nb0 = fmaf(w2, e.z, nb0); nb0 = fmaf(w3, e.w, nb0); db0 += w2 + w3;
                na1 = fmaf(w4, e.z, na1); na1 = fmaf(w5, e.w, na1); da1 += w4 + w5;
                nb1 = fmaf(w6, e.z, nb1); nb1 = fmaf(w7, e.w, nb1); db1 += w6 + w7;
            }
        }
        __syncthreads();
    }

    #pragma unroll
    for (int o = 1; o <= 2; o <<= 1) {
        na0 += __shfl_xor_sync(~0u, na0, o); da0 += __shfl_xor_sync(~0u, da0, o);
        nb0 += __shfl_xor_sync(~0u, nb0, o); db0 += __shfl_xor_sync(~0u, db0, o);
        na1 += __shfl_xor_sync(~0u, na1, o); da1 += __shfl_xor_sync(~0u, da1, o);
        nb1 += __shfl_xor_sync(~0u, nb1, o); db1 += __shfl_xor_sync(~0u, db1, o);
    }
    if ((lane & 3) == 0) {
        int q = qbase + qg;
        g_pnum[split][q]      = na0; g_pden[split][q]      = da0;
        g_pnum[split][q + 8]  = nb0; g_pden[split][q + 8]  = db0;
        g_pnum[split][q + 16] = na1; g_pden[split][q + 16] = da1;
        g_pnum[split][q + 24] = nb1; g_pden[split][q + 24] = db1;
    }
}

// ---------------- fused reduce + final (device-wide arrival barrier) ----------------
__global__ void k_redfin(const float* __restrict__ sig, float* __restrict__ out, int m) {
    __shared__ float s_rmin[4], s_rmax[4], s_smin[4], s_smax[4];
    int q = blockIdx.x * blockDim.x + threadIdx.x;
    float rx = 0.f, sg = 0.f;
    float rmn = 3.4e38f, rmx = -3.4e38f, smn = 3.4e38f, smx = -3.4e38f;
    if (q < m) {
        float num = 0.f, den = 0.f;
        #pragma unroll
        for (int s = 0; s < TSMAX; s++) { num += g_pnum[s][q]; den += g_pden[s][q]; }
        rx = num / (den + EPSV);
        sg = sig[q];
        rmn = rx; rmx = rx; smn = sg; smx = sg;
    }
    float wr0 = warp_min(rmn), wr1 = warp_max(rmx), ws0 = warp_min(smn), ws1 = warp_max(smx);
    int w = threadIdx.x >> 5, l = threadIdx.x & 31, nw = blockDim.x >> 5;
    if (l == 0) { s_rmin[w] = wr0; s_rmax[w] = wr1; s_smin[w] = ws0; s_smax[w] = ws1; }
    __syncthreads();
    if (threadIdx.x == 0) {
        float a = s_rmin[0], b = s_rmax[0], cc = s_smin[0], d = s_smax[0];
        for (int i = 1; i < nw; i++) {
            a = fminf(a, s_rmin[i]); b = fmaxf(b, s_rmax[i]);
            cc = fminf(cc, s_smin[i]); d = fmaxf(d, s_smax[i]);
        }
        atomicMin(&g_rmin, fenc(a)); atomicMax(&g_rmax, fenc(b));
        atomicMin(&g_smin, fenc(cc)); atomicMax(&g_smax, fenc(d));
        __threadfence();
        atomicAdd(&g_cnt, 1u);
        while (atomicAdd(&g_cnt, 0u) < gridDim.x) { }
    }
    __syncthreads();
    if (q >= m) return;
    float t1 = 0.5f * (rx - fdec(g_rmin)) / (fdec(g_rmax) - fdec(g_rmin) + EPSV);
    float t2 = 0.5f * (sg - fdec(g_smin)) / (fdec(g_smax) - fdec(g_smin) + EPSV);
    out[q] = t1 + t2;
}

// ---------------- launch ----------------
extern "C" void kernel_launch(void* const* d_in, const int* in_sizes, int n_in,
                              void* d_out, int out_size) {
    const float* x   = (const float*)d_in[0];
    const float* tx  = (const float*)d_in[1];
    const float* tr  = (const float*)d_in[2];
    const float* sig = (const float*)d_in[3];
    int m = in_sizes[0] / D;   // 16384
    int n = in_sizes[1] / D;   // 8192

    k_prepbw<<<BWB + (m + n) * 8 / 256, 256>>>(x, tx, tr, m, n);
    k_main_mma<<<64 * TSMAX, 256>>>(n);
    k_redfin<<<m / 128, 128>>>(sig, (float*)d_out, m);
}

// round 17
// speedup vs baseline: 1.0491x; 1.0491x over previous
#include <cuda_runtime.h>
#include <cuda_fp16.h>
#include <math.h>

#define D        32
#define TSMAX    9
#define NTT      128           // train per tile
#define MQ       128           // queries per CTA
#define M_MAX    16384
#define N_MAX    8192
#define EPSV     1e-8f
#define BWB      64

// smem pitch-80 rows. Buf: Bh[0,10240) ext[10240,11264)
#define PITCH    80
#define OFFEXT   10240
#define BUFSZ    11264
#define SMEMSZ   (2*BUFSZ)     // A staging (10240) aliases buffer 0 pre-loop

__device__ float        g_cl;
__device__ __half       g_Ah[M_MAX * D];    // fp16(x)
__device__ __half       g_Bh[N_MAX * D];    // fp16(t)
__device__ float4       g_ext4[N_MAX / 2];  // {t2q_even, t2q_odd, r_even, r_odd}
__device__ float        g_qe[M_MAX];        // q2 from quantized
__device__ double       g_bws [BWB * D];
__device__ double       g_bws2[BWB * D];
__device__ float        g_pnum[TSMAX][M_MAX];
__device__ float        g_pden[TSMAX][M_MAX];
__device__ unsigned int g_rmin, g_rmax, g_smin, g_smax;
__device__ unsigned int g_cnt;

// ---------------- helpers ----------------
__device__ __forceinline__ unsigned long long pack2(float lo, float hi) {
    unsigned long long r; asm("mov.b64 %0, {%1, %2};" : "=l"(r) : "f"(lo), "f"(hi)); return r;
}
__device__ __forceinline__ unsigned long long dup2(float v) {
    unsigned long long r; asm("mov.b64 %0, {%1, %1};" : "=l"(r) : "f"(v)); return r;
}
__device__ __forceinline__ unsigned long long fma2(unsigned long long a, unsigned long long b, unsigned long long c) {
    unsigned long long d; asm("fma.rn.f32x2 %0, %1, %2, %3;" : "=l"(d) : "l"(a), "l"(b), "l"(c)); return d;
}
__device__ __forceinline__ float2 unpack2(unsigned long long p) {
    float2 f; asm("mov.b64 {%0, %1}, %2;" : "=f"(f.x), "=f"(f.y) : "l"(p)); return f;
}
__device__ __forceinline__ float ex2f(float a) {
    float r; asm("ex2.approx.f32 %0, %1;" : "=f"(r) : "f"(a)); return r;
}
__device__ __forceinline__ void cp16(unsigned dst, const void* src) {
    asm volatile("cp.async.ca.shared.global [%0], [%1], 16;" :: "r"(dst), "l"(src));
}
__device__ __forceinline__ unsigned fenc(float f) {
    unsigned u = __float_as_uint(f); return (u & 0x80000000u) ? ~u : (u | 0x80000000u);
}
__device__ __forceinline__ float fdec(unsigned u) {
    u = (u & 0x80000000u) ? (u & 0x7fffffffu) : ~u; return __uint_as_float(u);
}
__device__ __forceinline__ float warp_min(float v) {
    #pragma unroll
    for (int o = 16; o; o >>= 1) v = fminf(v, __shfl_xor_sync(~0u, v, o));
    return v;
}
__device__ __forceinline__ float warp_max(float v) {
    #pragma unroll
    for (int o = 16; o; o >>= 1) v = fmaxf(v, __shfl_xor_sync(~0u, v, o));
    return v;
}
__device__ __forceinline__ void ldmx4(unsigned* r, unsigned addr) {
    asm volatile("ldmatrix.sync.aligned.m8n8.x4.shared.b16 {%0,%1,%2,%3}, [%4];"
                 : "=r"(r[0]), "=r"(r[1]), "=r"(r[2]), "=r"(r[3]) : "r"(addr));
}
__device__ __forceinline__ void mma_f16(float* c, const unsigned* a, unsigned b0, unsigned b1) {
    asm volatile("mma.sync.aligned.m16n8k16.row.col.f32.f16.f16.f32 "
                 "{%0,%1,%2,%3}, {%4,%5,%6,%7}, {%8,%9}, {%0,%1,%2,%3};"
                 : "+f"(c[0]), "+f"(c[1]), "+f"(c[2]), "+f"(c[3])
                 : "r"(a[0]), "r"(a[1]), "r"(a[2]), "r"(a[3]), "r"(b0), "r"(b1));
}

// ---------------- fused prep + bandwidth phase 1 (MLP=4 quantize path) --------
// blocks 0..63: per-dim bandwidth partials; blocks 64..255: quantize 4 units/thread
__global__ void k_prepbw(const float* __restrict__ x, const float* __restrict__ tx,
                         const float* __restrict__ tr, int m, int n) {
    __shared__ double sds[8][8][4], sds2[8][8][4];
    const int tid = threadIdx.x;
    if (blockIdx.x < BWB) {
        const int b = blockIdx.x;
        const float4* tx4 = (const float4*)tx;
        double s[4] = {0,0,0,0}, s2[4] = {0,0,0,0};
        #pragma unroll
        for (int it = 0; it < 4; it++) {
            float4 v = tx4[(size_t)(b * 128 + it * 32) * 8 + tid];
            double vx = v.x, vy = v.y, vz = v.z, vw = v.w;
            s[0] += vx; s2[0] += vx*vx; s[1] += vy; s2[1] += vy*vy;
            s[2] += vz; s2[2] += vz*vz; s[3] += vw; s2[3] += vw*vw;
        }
        #pragma unroll
        for (int o = 8; o <= 16; o <<= 1)
            #pragma unroll
            for (int k = 0; k < 4; k++) {
                s[k]  += __shfl_xor_sync(~0u, s[k],  o);
                s2[k] += __shfl_xor_sync(~0u, s2[k], o);
            }
        int w = tid >> 5, l = tid & 31;
        if (l < 8)
            #pragma unroll
            for (int k = 0; k < 4; k++) { sds[w][l][k] = s[k]; sds2[w][l][k] = s2[k]; }
        __syncthreads();
        if (tid < 8)
            #pragma unroll
            for (int k = 0; k < 4; k++) {
                double a = 0, a2 = 0;
                #pragma unroll
                for (int ww = 0; ww < 8; ww++) { a += sds[ww][tid][k]; a2 += sds2[ww][tid][k]; }
                g_bws[b * D + tid * 4 + k] = a; g_bws2[b * D + tid * 4 + k] = a2;
            }
        return;
    }
    // quantize: block handles 1024 units (4 per thread, front-batched loads)
    const int ub = (blockIdx.x - BWB) * 1024;        // first unit of this block
    const bool isq = (ub < m * 8);                   // block-uniform (boundary aligned)
    const float4* src = isq ? (const float4*)x : (const float4*)tx;
    const int rbase = isq ? 0 : m;                   // row offset for global ids
    const int u0 = isq ? ub : ub - m * 8;
    float4 v[4];
    #pragma unroll
    for (int k = 0; k < 4; k++) v[k] = src[(size_t)u0 + k * 256 + tid];
    #pragma unroll
    for (int k = 0; k < 4; k++) {
        int u = u0 + k * 256 + tid;
        int row = u >> 3, g = u & 7;
        __half hx = __float2half_rn(v[k].x), hy = __float2half_rn(v[k].y);
        __half hz = __float2half_rn(v[k].z), hw = __float2half_rn(v[k].w);
        float qx = __half2float(hx), qy = __half2float(hy);
        float qz = __half2float(hz), qw = __half2float(hw);
        float s = fmaf(qx, qx, fmaf(qy, qy, fmaf(qz, qz, qw * qw)));
        s += __shfl_xor_sync(~0u, s, 1);
        s += __shfl_xor_sync(~0u, s, 2);
        s += __shfl_xor_sync(~0u, s, 4);
        uint2 hi;
        hi.x = (unsigned)__half_as_ushort(hx) | ((unsigned)__half_as_ushort(hy) << 16);
        hi.y = (unsigned)__half_as_ushort(hz) | ((unsigned)__half_as_ushort(hw) << 16);
        if (isq) {
            ((uint2*)g_Ah)[(size_t)u] = hi;
            if (g == 0) g_qe[row] = s;
        } else {
            ((uint2*)g_Bh)[(size_t)u] = hi;
            if (g == 0) {
                float* e = (float*)&g_ext4[row >> 1];
                if (row & 1) { e[1] = s; e[3] = tr[row]; }
                else         { e[0] = s; e[2] = tr[row]; }
            }
        }
        (void)rbase;
    }
}

// ---------------- bandwidth phase 2 + scalar init ----------------
__global__ void k_bw2(int n) {
    int d = threadIdx.x;
    double s = 0, s2 = 0;
    for (int b = 0; b < BWB; b++) { s += g_bws[b * D + d]; s2 += g_bws2[b * D + d]; }
    double mean = s / n, var = (s2 - n * mean * mean) / (n - 1);
    double sd = sqrt(var > 0.0 ? var : 0.0);
    #pragma unroll
    for (int o = 16; o; o >>= 1) sd += __shfl_xor_sync(~0u, sd, o);
    if (d == 0) {
        double bw = (sd / D) * exp(-log((double)n) / (D + 4));
        g_cl = (float)(1.0 / (2.0 * bw * bw) * 1.4426950408889634);
        g_rmin = ~0u; g_rmax = 0u; g_smin = ~0u; g_smax = 0u;
        g_cnt = 0u;
    }
}

// ---------------- HMMA KDE mainloop: 4 warps x 32 queries, occ 8 ----------------
__device__ __forceinline__ void load_tile(unsigned sb, int g, int b, int tid) {
    unsigned base = sb + b * BUFSZ;
    const __half* sh = g_Bh + (size_t)g * NTT * D;
    #pragma unroll
    for (int i = 0; i < 4; i++) {
        int idx = tid + i * 128, row = idx >> 2, c = idx & 3;
        cp16(base + row * PITCH + c * 16, sh + row * D + c * 8);
    }
    if (tid < 64) cp16(base + OFFEXT + tid * 16, g_ext4 + (size_t)g * 64 + tid);
    asm volatile("cp.async.commit_group;" ::: "memory");
}

__global__ void __launch_bounds__(128, 8)
k_main_mma(int n) {
    __shared__ __align__(16) char smem[SMEMSZ];
    unsigned sb = (unsigned)__cvta_generic_to_shared(smem);
    const int tid = threadIdx.x, w = tid >> 5, lane = tid & 31;
    const int qblk  = blockIdx.x & 127;
    const int split = blockIdx.x >> 7;               // 0..8, grid = 1152
    const int NTtot = n / NTT;                       // 64
    const int tb_lo = (split * NTtot) / TSMAX;
    const int tb_hi = ((split + 1) * NTtot) / TSMAX;

    #pragma unroll
    for (int i = 0; i < 4; i++) {
        int idx = tid + i * 128, row = idx >> 2, c = idx & 3;
        cp16(sb + row * PITCH + c * 16, g_Ah + (size_t)(qblk * MQ + row) * D + c * 8);
    }
    asm volatile("cp.async.commit_group;" ::: "memory");
    asm volatile("cp.async.wait_group 0;" ::: "memory");
    __syncthreads();

    unsigned ah0[2][4], ah1[2][4];
    {
        unsigned rowsel = lane & 15, colb = (lane >> 4) * 16;
        unsigned ab0 = sb + (w * 32 + rowsel) * PITCH + colb;
        unsigned ab1 = ab0 + 16 * PITCH;
        ldmx4(ah0[0], ab0);
        ldmx4(ah0[1], ab0 + 32);
        ldmx4(ah1[0], ab1);
        ldmx4(ah1[1], ab1 + 32);
    }
    const int qg = lane >> 2;
    const float cl = g_cl;
    const unsigned long long negcl2 = dup2(-cl);
    const unsigned long long K2d    = dup2(cl + cl);
    const int qbase = qblk * MQ + w * 32;
    const unsigned long long cqa0 = dup2(-cl * g_qe[qbase + qg]);
    const unsigned long long cqb0 = dup2(-cl * g_qe[qbase + qg + 8]);
    const unsigned long long cqa1 = dup2(-cl * g_qe[qbase + qg + 16]);
    const unsigned long long cqb1 = dup2(-cl * g_qe[qbase + qg + 24]);
    __syncthreads();

    load_tile(sb, tb_lo, 0, tid);

    float na0 = 0.f, da0 = 0.f, nb0 = 0.f, db0 = 0.f;
    float na1 = 0.f, da1 = 0.f, nb1 = 0.f, db1 = 0.f;

    const unsigned browAdd = (lane >> 4) * 8 + (lane & 7);
    const unsigned bcolb   = ((lane >> 3) & 1) * 16;

    for (int tb = tb_lo; tb < tb_hi; tb++) {
        const int buf = (tb - tb_lo) & 1;
        if (tb + 1 < tb_hi) {
            load_tile(sb, tb + 1, buf ^ 1, tid);
            asm volatile("cp.async.wait_group 1;" ::: "memory");
        } else {
            asm volatile("cp.async.wait_group 0;" ::: "memory");
        }
        __syncthreads();

        const unsigned bbase = sb + buf * BUFSZ;
        const float4* ext = (const float4*)(smem + buf * BUFSZ + OFFEXT);

        #pragma unroll
        for (int np = 0; np < 8; np++) {
            const unsigned rb = bbase + (np * 16 + browAdd) * PITCH + bcolb;
            float c0[2][4], c1[2][4];
            #pragma unroll
            for (int s = 0; s < 2; s++)
                #pragma unroll
                for (int k = 0; k < 4; k++) { c0[s][k] = 0.f; c1[s][k] = 0.f; }

            #pragma unroll
            for (int ks = 0; ks < 2; ks++) {
                unsigned bv[4];
                ldmx4(bv, rb + ks * 32);
                mma_f16(c0[0], ah0[ks], bv[0], bv[1]);
                mma_f16(c0[1], ah0[ks], bv[2], bv[3]);
                mma_f16(c1[0], ah1[ks], bv[0], bv[1]);
                mma_f16(c1[1], ah1[ks], bv[2], bv[3]);
            }

            #pragma unroll
            for (int ns = 0; ns < 2; ns++) {
                float4 e = ext[(np * 2 + ns) * 4 + (lane & 3)];
                unsigned long long t2p = pack2(e.x, e.y);
                unsigned long long ba0 = fma2(t2p, negcl2, cqa0);
                unsigned long long bb0 = fma2(t2p, negcl2, cqb0);
                unsigned long long ba1 = fma2(t2p, negcl2, cqa1);
                unsigned long long bb1 = fma2(t2p, negcl2, cqb1);
                unsigned long long pa0 = fma2(pack2(c0[ns][0], c0[ns][1]), K2d, ba0);
                unsigned long long pb0 = fma2(pack2(c0[ns][2], c0[ns][3]), K2d, bb0);
                unsigned long long pa1 = fma2(pack2(c1[ns][0], c1[ns][1]), K2d, ba1);
                unsigned long long pb1 = fma2(pack2(c1[ns][2], c1[ns][3]), K2d, bb1);
                float2 f0 = unpack2(pa0), f1 = unpack2(pb0);
                float2 f2 = unpack2(pa1), f3 = unpack2(pb1);
                float w0 = ex2f(f0.x), w1 = ex2f(f0.y);
                float w2 = ex2f(f1.x), w3 = ex2f(f1.y);
                float w4 = ex2f(f2.x), w5 = ex2f(f2.y);
                float w6 = ex2f(f3.x), w7 = ex2f(f3.y);
                na0 = fmaf(w0, e.z, na0); na0 = fmaf(w1, e.w, na0); da0 += w0 + w1;
                nb0 = fmaf(w2, e.z, nb0); nb0 = fmaf(w3, e.w, nb0); db0 += w2 + w3;
                na1 = fmaf(w4, e.z, na1); na1 = fmaf(w5, e.w, na1); da1 += w4 + w5;
                nb1 = fmaf(w6, e.z, nb1); nb1 = fmaf(w7, e.w, nb1); db1 += w6 + w7;
            }
        }
        __syncthreads();
    }

    #pragma unroll
    for (int o = 1; o <= 2; o <<= 1) {
        na0 += __shfl_xor_sync(~0u, na0, o); da0 += __shfl_xor_sync(~0u, da0, o);
        nb0 += __shfl_xor_sync(~0u, nb0, o); db0 += __shfl_xor_sync(~0u, db0, o);
        na1 += __shfl_xor_sync(~0u, na1, o); da1 += __shfl_xor_sync(~0u, da1, o);
        nb1 += __shfl_xor_sync(~0u, nb1, o); db1 += __shfl_xor_sync(~0u, db1, o);
    }
    if ((lane & 3) == 0) {
        int q = qbase + qg;
        g_pnum[split][q]      = na0; g_pden[split][q]      = da0;
        g_pnum[split][q + 8]  = nb0; g_pden[split][q + 8]  = db0;
        g_pnum[split][q + 16] = na1; g_pden[split][q + 16] = da1;
        g_pnum[split][q + 24] = nb1; g_pden[split][q + 24] = db1;
    }
}

// ---------------- fused reduce + final (device-wide arrival barrier) ----------------
__global__ void k_redfin(const float* __restrict__ sig, float* __restrict__ out, int m) {
    __shared__ float s_rmin[8], s_rmax[8], s_smin[8], s_smax[8];
    int q = blockIdx.x * blockDim.x + threadIdx.x;
    float rx = 0.f, sg = 0.f;
    float rmn = 3.4e38f, rmx = -3.4e38f, smn = 3.4e38f, smx = -3.4e38f;
    if (q < m) {
        float num = 0.f, den = 0.f;
        #pragma unroll
        for (int s = 0; s < TSMAX; s++) { num += g_pnum[s][q]; den += g_pden[s][q]; }
        rx = num / (den + EPSV);
        sg = sig[q];
        rmn = rx; rmx = rx; smn = sg; smx = sg;
    }
    float wr0 = warp_min(rmn), wr1 = warp_max(rmx), ws0 = warp_min(smn), ws1 = warp_max(smx);
    int w = threadIdx.x >> 5, l = threadIdx.x & 31, nw = blockDim.x >> 5;
    if (l == 0) { s_rmin[w] = wr0; s_rmax[w] = wr1; s_smin[w] = ws0; s_smax[w] = ws1; }
    __syncthreads();
    if (threadIdx.x == 0) {
        float a = s_rmin[0], b = s_rmax[0], cc = s_smin[0], d = s_smax[0];
        for (int i = 1; i < nw; i++) {
            a = fminf(a, s_rmin[i]); b = fmaxf(b, s_rmax[i]);
            cc = fminf(cc, s_smin[i]); d = fmaxf(d, s_smax[i]);
        }
        atomicMin(&g_rmin, fenc(a)); atomicMax(&g_rmax, fenc(b));
        atomicMin(&g_smin, fenc(cc)); atomicMax(&g_smax, fenc(d));
        __threadfence();
        atomicAdd(&g_cnt, 1u);
        while (atomicAdd(&g_cnt, 0u) < gridDim.x) { }
    }
    __syncthreads();
    if (q >= m) return;
    float t1 = 0.5f * (rx - fdec(g_rmin)) / (fdec(g_rmax) - fdec(g_rmin) + EPSV);
    float t2 = 0.5f * (sg - fdec(g_smin)) / (fdec(g_smax) - fdec(g_smin) + EPSV);
    out[q] = t1 + t2;
}

// ---------------- launch ----------------
extern "C" void kernel_launch(void* const* d_in, const int* in_sizes, int n_in,
                              void* d_out, int out_size) {
    const float* x   = (const float*)d_in[0];
    const float* tx  = (const float*)d_in[1];
    const float* tr  = (const float*)d_in[2];
    const float* sig = (const float*)d_in[3];
    int m = in_sizes[0] / D;   // 16384
    int n = in_sizes[1] / D;   // 8192

    k_prepbw<<<BWB + (m + n) * 8 / 1024, 256>>>(x, tx, tr, m, n);
    k_bw2<<<1, 32>>>(n);
    k_main_mma<<<128 * TSMAX, 128>>>(n);
    k_redfin<<<(m + 255) / 256, 256>>>(sig, (float*)d_out, m);
}